// round 9
// baseline (speedup 1.0000x reference)
#include <cuda_runtime.h>
#include <cuda_fp16.h>

// Radon forward projection, sm_103a — round 9.
// R8 failed because its row swizzle was additive-LINEAR mod 16 (equivalent to a
// stride change): near-vertical angles collapsed to 4-way conflicts. This round
// keeps R7's odd-stride single-index addressing and adds a NONLINEAR row hash
// h(r) = (r ^ (r>>2)) & 15 on stride 147 (rows can't overlap: 147 >= 131+16).
// Horizontal band (row const per warp) unaffected; vertical band decorrelated.

#define STRIDE_E 147                          // odd, >= 131+15+1 (no row overlap)
#define SMEM_ELEMS (131 * STRIDE_E + 16)      // 19273 entries (8 B each)
#define SMEM_BYTES (SMEM_ELEMS * 8 + 64)      // ~154 KB + trig table

#define N_ANG 285
#define N_DET 183
#define SINO  (N_ANG * N_DET)                 // 52155
#define NTHR  768

typedef unsigned long long u64;

__device__ __forceinline__ u64 pk2(float x, float y) {
    u64 u; asm("mov.b64 %0, {%1, %2};" : "=l"(u) : "f"(x), "f"(y)); return u;
}
__device__ __forceinline__ void upk2(u64 u, float& x, float& y) {
    asm("mov.b64 {%0, %1}, %2;" : "=f"(x), "=f"(y) : "l"(u));
}
__device__ __forceinline__ u64 fma2_(u64 a, u64 b, u64 c) {
    u64 d; asm("fma.rn.f32x2 %0, %1, %2, %3;" : "=l"(d) : "l"(a), "l"(b), "l"(c)); return d;
}
__device__ __forceinline__ u64 add2_(u64 a, u64 b) {
    u64 d; asm("add.rn.f32x2 %0, %1, %2;" : "=l"(d) : "l"(a), "l"(b)); return d;
}
__device__ __forceinline__ __half2 as_h2(unsigned u) {
    __half2 h; asm("mov.b32 %0, %1;" : "=r"(reinterpret_cast<unsigned&>(h)) : "r"(u)); return h;
}
#define HROW(r) ((((r) ^ ((r) >> 2))) & 15)

__global__ __launch_bounds__(NTHR, 1)
void radon_fp_kernel(const float* __restrict__ x, float* __restrict__ out)
{
    extern __shared__ u64 imgs[];
    float2* trig = (float2*)(imgs + SMEM_ELEMS);

    const int tid = threadIdx.x;
    const int bg  = blockIdx.y;          // batch group: batches 4bg .. 4bg+3
    const int sub = tid / 192;           // which of 4 concurrent angles (0..3)
    const int det = tid % 192;

    const float* gx0 = x + (4 * bg)     * 16384;
    const float* gx1 = x + (4 * bg + 1) * 16384;
    const float* gx2 = x + (4 * bg + 2) * 16384;
    const float* gx3 = x + (4 * bg + 3) * 16384;

    // Fill padded 4-batch fp16 image. Array coords (ar, ac) = pixel (ar-1, ac-1),
    // ar, ac in [0, 130]; stored at ar*147 + h(ar) + ac. Gap entries never read.
    for (int e = tid; e < 131 * 131; e += NTHR) {
        int ar = e / 131;
        int ac = e - ar * 131;
        int pr = ar - 1, pc = ac - 1;
        bool in = ((unsigned)pr < 128u) & ((unsigned)pc < 128u);
        int gi = pr * 128 + pc;
        float v0 = in ? gx0[gi] : 0.0f;
        float v1 = in ? gx1[gi] : 0.0f;
        float v2 = in ? gx2[gi] : 0.0f;
        float v3 = in ? gx3[gi] : 0.0f;
        __half2 L = __floats2half2_rn(v0, v1);
        __half2 H = __floats2half2_rn(v2, v3);
        unsigned lo = reinterpret_cast<unsigned&>(L);
        unsigned hi = reinterpret_cast<unsigned&>(H);
        imgs[ar * STRIDE_E + HROW(ar) + ac] = ((u64)hi << 32) | (u64)lo;
    }
    // Double-precision trig for this block's 4 angles.
    if (tid < 4) {
        int a = 4 * blockIdx.x + tid;
        if (a < N_ANG) {
            double sd, cd;
            sincospi((a + 0.5) / 285.0, &sd, &cd);
            trig[tid] = make_float2((float)sd, (float)cd);
        }
    }
    __syncthreads();

    // Constants (double-derived)
    const float RHOf = 28.284271247461902f;
    const float KD   = 0.47140452079103173f;        // DT/DX, DX = 0.3125
    const float t0c  = -28.284271247461902f + 0.5f * 0.14731391274719688f;
    const float scale = 0.012276159395599740f;      // DT/12
    const float s = fmaf((float)det + 0.5f, 2.0f * RHOf / 183.0f, -RHOf);

    const u64 BIG2   = pk2( 8388608.f,  8388608.f);
    const u64 nBIG2  = pk2(-8388608.f, -8388608.f);
    const u64 half2c = pk2(0.5f, 0.5f);
    const u64 neg1   = pk2(-1.f, -1.f);
    const u64 one2   = pk2(1.f, 1.f);
    const uint2* img2 = (const uint2*)imgs;

    const int a = 4 * blockIdx.x + sub;
    if (det < N_DET && a < N_ANG) {
        float2 sc = trig[sub];
        float sn = sc.x, cs = sc.y;
        float d0 = KD * cs;
        float d1 = KD * sn;
        // i0 = (-s*sn + t*cs + 20)*3.2 - 0.5, t = t0c + k*DT
        float c0 = fmaf(-s, sn, fmaf(t0c, cs, 20.0f)) * 3.2f - 0.5f;
        float c1 = fmaf( s, cs, fmaf(t0c, sn, 20.0f)) * 3.2f - 0.5f;

        // Valid window (content zero outside i in (-1, 128); safe to 129.49)
        const float LO = -0.999f, HI = 128.01f;
        float ra = (LO - c0) / d0, rb = (HI - c0) / d0;
        float klo = fmaxf(0.0f,  fminf(ra, rb));
        float khi = fminf(383.0f, fmaxf(ra, rb));
        ra = (LO - c1) / d1; rb = (HI - c1) / d1;
        klo = fmaxf(klo, fminf(ra, rb));
        khi = fminf(khi, fmaxf(ra, rb));
        int k0 = (int)ceilf(klo);
        int k1 = (int)floorf(khi);

        u64 d01  = pk2(d0, d1);
        u64 c01m = pk2(c0 + 1.5f, c1 + 1.5f);   // t = i + 1.5
        u64 kf2  = pk2((float)k0, (float)k0);
        u64 accA = 0ull;                        // batches 0,1 (fp32 pair)
        u64 accB = 0ull;                        // batches 2,3

        #pragma unroll 4
        for (int k = k0; k <= k1; ++k) {
            u64 t01  = fma2_(kf2, d01, c01m);        // i+1.5, both axes
            u64 y01  = add2_(t01, BIG2);             // round-to-int in mantissa
            u64 fl01 = add2_(y01, nBIG2);            // round(t) = floor(i)+2
            u64 fr01 = add2_(fma2_(fl01, neg1, t01), half2c); // frac in [0,1]
            kf2 = add2_(kf2, one2);
            int n0 = (int)((unsigned)y01 & 255u);          // floor(i0)+2 in [1,130]
            int n1 = (int)((unsigned)(y01 >> 32) & 255u);  // floor(i1)+2
            // Rows accessed: R = n0-1 and n0; cols C = n1-1, C+1.
            // addr(r, c) = r*147 + h(r) + c,  h nonlinear mod 16.
            int r0 = n0 - 1;
            int h0 = HROW(r0);
            int h1 = HROW(n0);
            int base = n0 * STRIDE_E + n1;               // = (r0+1)*147 + n1
            const uint2* pr0 = img2 + (base + h0 - (STRIDE_E + 1)); // row R,  col C
            const uint2* pr1 = img2 + (base + h1 - 1);              // row R+1, col C
            uint2 q00 = pr0[0];
            uint2 q01 = pr0[1];
            uint2 q10 = pr1[0];
            uint2 q11 = pr1[1];
            float f0, f1; upk2(fr01, f0, f1);
            __half2 f0h = __float2half2_rn(f0);
            __half2 f1h = __float2half2_rn(f1);
            // batches 0,1 (low words)
            {
                __half2 a00 = as_h2(q00.x), a01 = as_h2(q01.x);
                __half2 a10 = as_h2(q10.x), a11 = as_h2(q11.x);
                __half2 m0h = __hfma2(f1h, __hsub2(a01, a00), a00);
                __half2 m1h = __hfma2(f1h, __hsub2(a11, a10), a10);
                __half2 r   = __hfma2(f0h, __hsub2(m1h, m0h), m0h);
                accA = add2_(accA, pk2(__low2float(r), __high2float(r)));
            }
            // batches 2,3 (high words)
            {
                __half2 b00 = as_h2(q00.y), b01 = as_h2(q01.y);
                __half2 b10 = as_h2(q10.y), b11 = as_h2(q11.y);
                __half2 m0h = __hfma2(f1h, __hsub2(b01, b00), b00);
                __half2 m1h = __hfma2(f1h, __hsub2(b11, b10), b10);
                __half2 r   = __hfma2(f0h, __hsub2(m1h, m0h), m0h);
                accB = add2_(accB, pk2(__low2float(r), __high2float(r)));
            }
        }

        int ob = ((4 * bg) * N_ANG + a) * N_DET + det;
        float o0, o1, o2, o3;
        upk2(accA, o0, o1);
        upk2(accB, o2, o3);
        out[ob]            = o0 * scale;
        out[ob + SINO]     = o1 * scale;
        out[ob + 2 * SINO] = o2 * scale;
        out[ob + 3 * SINO] = o3 * scale;
    }
}

extern "C" void kernel_launch(void* const* d_in, const int* in_sizes, int n_in,
                              void* d_out, int out_size)
{
    const float* x = (const float*)d_in[0];
    float* out = (float*)d_out;

    static bool attr_set = false;
    if (!attr_set) {
        cudaFuncSetAttribute(radon_fp_kernel,
                             cudaFuncAttributeMaxDynamicSharedMemorySize, SMEM_BYTES);
        attr_set = true;
    }

    dim3 grid(72, 2);    // 72 angle-quads x 2 batch-groups = 144 blocks (1 wave)
    radon_fp_kernel<<<grid, NTHR, SMEM_BYTES>>>(x, out);
}

// round 10
// speedup vs baseline: 1.8047x; 1.8047x over previous
#include <cuda_runtime.h>
#include <cuda_fp16.h>

// Radon forward projection, sm_103a — round 10.
// R8/R9 proved conflict-shaping is a dead end. This round reverts to the R7
// layout (stride 131, fp16x4 taps, half2 blend) and hides LDS latency with a
// 1-deep software prefetch: iteration k issues k+1's 4 LDS.64 before k's math.
// A 132-entry dead pad in front of the image makes the k1+1 overshoot prefetch
// memory-safe at zero per-iter cost.

#define STRIDE_E 131
#define PAD_E    132                          // front pad absorbs the -132 fold
#define IMG_E    (131 * STRIDE_E)             // 17161 image entries
#define SMEM_ELEMS (PAD_E + IMG_E)
#define SMEM_BYTES (SMEM_ELEMS * 8 + 64)      // + trig table

#define N_ANG 285
#define N_DET 183
#define SINO  (N_ANG * N_DET)                 // 52155
#define NTHR  768

typedef unsigned long long u64;

__device__ __forceinline__ u64 pk2(float x, float y) {
    u64 u; asm("mov.b64 %0, {%1, %2};" : "=l"(u) : "f"(x), "f"(y)); return u;
}
__device__ __forceinline__ void upk2(u64 u, float& x, float& y) {
    asm("mov.b64 {%0, %1}, %2;" : "=f"(x), "=f"(y) : "l"(u));
}
__device__ __forceinline__ u64 fma2_(u64 a, u64 b, u64 c) {
    u64 d; asm("fma.rn.f32x2 %0, %1, %2, %3;" : "=l"(d) : "l"(a), "l"(b), "l"(c)); return d;
}
__device__ __forceinline__ u64 add2_(u64 a, u64 b) {
    u64 d; asm("add.rn.f32x2 %0, %1, %2;" : "=l"(d) : "l"(a), "l"(b)); return d;
}
__device__ __forceinline__ __half2 as_h2(unsigned u) {
    __half2 h; asm("mov.b32 %0, %1;" : "=r"(reinterpret_cast<unsigned&>(h)) : "r"(u)); return h;
}

__global__ __launch_bounds__(NTHR, 1)
void radon_fp_kernel(const float* __restrict__ x, float* __restrict__ out)
{
    extern __shared__ u64 imgs[];
    float2* trig = (float2*)(imgs + SMEM_ELEMS);

    const int tid = threadIdx.x;
    const int bg  = blockIdx.y;          // batch group: batches 4bg .. 4bg+3
    const int sub = tid / 192;           // which of 4 concurrent angles (0..3)
    const int det = tid % 192;

    const float* gx0 = x + (4 * bg)     * 16384;
    const float* gx1 = x + (4 * bg + 1) * 16384;
    const float* gx2 = x + (4 * bg + 2) * 16384;
    const float* gx3 = x + (4 * bg + 3) * 16384;

    // Fill padded 4-batch fp16 image at offset PAD_E. Array coords (ar, ac) =
    // pixel (ar-1, ac-1), border 0. Front pad is never written (garbage only
    // ever read by the discarded final prefetch).
    for (int e = tid; e < 131 * 131; e += NTHR) {
        int ar = e / 131;
        int ac = e - ar * 131;
        int pr = ar - 1, pc = ac - 1;
        bool in = ((unsigned)pr < 128u) & ((unsigned)pc < 128u);
        int gi = pr * 128 + pc;
        float v0 = in ? gx0[gi] : 0.0f;
        float v1 = in ? gx1[gi] : 0.0f;
        float v2 = in ? gx2[gi] : 0.0f;
        float v3 = in ? gx3[gi] : 0.0f;
        __half2 L = __floats2half2_rn(v0, v1);
        __half2 H = __floats2half2_rn(v2, v3);
        unsigned lo = reinterpret_cast<unsigned&>(L);
        unsigned hi = reinterpret_cast<unsigned&>(H);
        imgs[PAD_E + ar * STRIDE_E + ac] = ((u64)hi << 32) | (u64)lo;
    }
    // Double-precision trig for this block's 4 angles.
    if (tid < 4) {
        int a = 4 * blockIdx.x + tid;
        if (a < N_ANG) {
            double sd, cd;
            sincospi((a + 0.5) / 285.0, &sd, &cd);
            trig[tid] = make_float2((float)sd, (float)cd);
        }
    }
    __syncthreads();

    // Constants (double-derived)
    const float RHOf = 28.284271247461902f;
    const float KD   = 0.47140452079103173f;        // DT/DX, DX = 0.3125
    const float t0c  = -28.284271247461902f + 0.5f * 0.14731391274719688f;
    const float scale = 0.012276159395599740f;      // DT/12
    const float s = fmaf((float)det + 0.5f, 2.0f * RHOf / 183.0f, -RHOf);

    const u64 BIG2   = pk2( 8388608.f,  8388608.f);
    const u64 nBIG2  = pk2(-8388608.f, -8388608.f);
    const u64 half2c = pk2(0.5f, 0.5f);
    const u64 neg1   = pk2(-1.f, -1.f);
    const u64 one2   = pk2(1.f, 1.f);
    // Image logical base: entry (n0-1, n1-1) at taps; folded offset:
    // addr = PAD_E + (n0-1)*131 + (n1-1) = n0*131 + n1 + (PAD_E - 132) = n0*131+n1.
    const uint2* img2 = (const uint2*)imgs;

    const int a = 4 * blockIdx.x + sub;
    if (det < N_DET && a < N_ANG) {
        float2 sc = trig[sub];
        float sn = sc.x, cs = sc.y;
        float d0 = KD * cs;
        float d1 = KD * sn;
        // i0 = (-s*sn + t*cs + 20)*3.2 - 0.5, t = t0c + k*DT
        float c0 = fmaf(-s, sn, fmaf(t0c, cs, 20.0f)) * 3.2f - 0.5f;
        float c1 = fmaf( s, cs, fmaf(t0c, sn, 20.0f)) * 3.2f - 0.5f;

        // Valid window (content zero outside i in (-1, 128); safe to 129.49)
        const float LO = -0.999f, HI = 128.01f;
        float ra = (LO - c0) / d0, rb = (HI - c0) / d0;
        float klo = fmaxf(0.0f,  fminf(ra, rb));
        float khi = fminf(383.0f, fmaxf(ra, rb));
        ra = (LO - c1) / d1; rb = (HI - c1) / d1;
        klo = fmaxf(klo, fminf(ra, rb));
        khi = fminf(khi, fmaxf(ra, rb));
        int k0 = (int)ceilf(klo);
        int k1 = (int)floorf(khi);

        u64 accA = 0ull;                        // batches 0,1 (fp32 pair)
        u64 accB = 0ull;                        // batches 2,3

        if (k0 <= k1) {
            u64 d01  = pk2(d0, d1);
            u64 c01m = pk2(c0 + 1.5f, c1 + 1.5f);   // t = i + 1.5
            u64 kf2  = pk2((float)k0, (float)k0);

            // Prologue: compute k0's frac + taps
            u64 t01  = fma2_(kf2, d01, c01m);
            u64 y01  = add2_(t01, BIG2);
            u64 fl01 = add2_(y01, nBIG2);
            u64 fr   = add2_(fma2_(fl01, neg1, t01), half2c);
            int n0 = (int)((unsigned)y01 & 255u);
            int n1 = (int)((unsigned)(y01 >> 32) & 255u);
            int idx = n0 * STRIDE_E + n1;
            uint2 q00 = img2[idx];
            uint2 q01 = img2[idx + 1];
            uint2 q10 = img2[idx + STRIDE_E];
            uint2 q11 = img2[idx + STRIDE_E + 1];

            #pragma unroll 4
            for (int k = k0; k <= k1; ++k) {
                // --- prefetch k+1 (final overshoot lands in [0, 130] rows/cols;
                //     front pad absorbs the lowest addresses; values discarded) ---
                kf2 = add2_(kf2, one2);
                u64 t_n  = fma2_(kf2, d01, c01m);
                u64 y_n  = add2_(t_n, BIG2);
                u64 fl_n = add2_(y_n, nBIG2);
                u64 fr_n = add2_(fma2_(fl_n, neg1, t_n), half2c);
                int m0 = (int)((unsigned)y_n & 255u);
                int m1 = (int)((unsigned)(y_n >> 32) & 255u);
                int idx_n = m0 * STRIDE_E + m1;
                uint2 p00 = img2[idx_n];
                uint2 p01 = img2[idx_n + 1];
                uint2 p10 = img2[idx_n + STRIDE_E];
                uint2 p11 = img2[idx_n + STRIDE_E + 1];

                // --- math on current taps ---
                float f0, f1; upk2(fr, f0, f1);
                __half2 f0h = __float2half2_rn(f0);
                __half2 f1h = __float2half2_rn(f1);
                {
                    __half2 a00 = as_h2(q00.x), a01 = as_h2(q01.x);
                    __half2 a10 = as_h2(q10.x), a11 = as_h2(q11.x);
                    __half2 m0h = __hfma2(f1h, __hsub2(a01, a00), a00);
                    __half2 m1h = __hfma2(f1h, __hsub2(a11, a10), a10);
                    __half2 r   = __hfma2(f0h, __hsub2(m1h, m0h), m0h);
                    accA = add2_(accA, pk2(__low2float(r), __high2float(r)));
                }
                {
                    __half2 b00 = as_h2(q00.y), b01 = as_h2(q01.y);
                    __half2 b10 = as_h2(q10.y), b11 = as_h2(q11.y);
                    __half2 m0h = __hfma2(f1h, __hsub2(b01, b00), b00);
                    __half2 m1h = __hfma2(f1h, __hsub2(b11, b10), b10);
                    __half2 r   = __hfma2(f0h, __hsub2(m1h, m0h), m0h);
                    accB = add2_(accB, pk2(__low2float(r), __high2float(r)));
                }

                // --- rotate pipeline ---
                fr = fr_n;
                q00 = p00; q01 = p01; q10 = p10; q11 = p11;
            }
        }

        int ob = ((4 * bg) * N_ANG + a) * N_DET + det;
        float o0, o1, o2, o3;
        upk2(accA, o0, o1);
        upk2(accB, o2, o3);
        out[ob]            = o0 * scale;
        out[ob + SINO]     = o1 * scale;
        out[ob + 2 * SINO] = o2 * scale;
        out[ob + 3 * SINO] = o3 * scale;
    }
}

extern "C" void kernel_launch(void* const* d_in, const int* in_sizes, int n_in,
                              void* d_out, int out_size)
{
    const float* x = (const float*)d_in[0];
    float* out = (float*)d_out;

    static bool attr_set = false;
    if (!attr_set) {
        cudaFuncSetAttribute(radon_fp_kernel,
                             cudaFuncAttributeMaxDynamicSharedMemorySize, SMEM_BYTES);
        attr_set = true;
    }

    dim3 grid(72, 2);    // 72 angle-quads x 2 batch-groups = 144 blocks (1 wave)
    radon_fp_kernel<<<grid, NTHR, SMEM_BYTES>>>(x, out);
}

// round 12
// speedup vs baseline: 1.8555x; 1.0282x over previous
#include <cuda_runtime.h>
#include <cuda_fp16.h>

// Radon forward projection, sm_103a — round 11.
// Per-block adaptive transpose: per-lane smem entry stride is
// 0.989*(cos - 131*sin); near-vertical angle blocks (45..135 deg) hit mod-16
// resonances (~1.6x conflicts). Those blocks store the image TRANSPOSED so the
// 131-stride multiplies cos instead -> lane stride ~ -sin ~ +-1, conflict-free.
// Inner loop is axis-symmetric; only the fill index and a (c,d) swap change.
// (R10 manual prefetch was neutral -> dropped; otherwise identical to R7.)

#define STRIDE_E 131
#define SMEM_ELEMS (131 * STRIDE_E)           // 17161 entries (8 B each)
#define SMEM_BYTES (SMEM_ELEMS * 8 + 64)      // + trig table

#define N_ANG 285
#define N_DET 183
#define SINO  (N_ANG * N_DET)                 // 52155
#define NTHR  768

typedef unsigned long long u64;

__device__ __forceinline__ u64 pk2(float x, float y) {
    u64 u; asm("mov.b64 %0, {%1, %2};" : "=l"(u) : "f"(x), "f"(y)); return u;
}
__device__ __forceinline__ void upk2(u64 u, float& x, float& y) {
    asm("mov.b64 {%0, %1}, %2;" : "=f"(x), "=f"(y) : "l"(u));
}
__device__ __forceinline__ u64 fma2_(u64 a, u64 b, u64 c) {
    u64 d; asm("fma.rn.f32x2 %0, %1, %2, %3;" : "=l"(d) : "l"(a), "l"(b), "l"(c)); return d;
}
__device__ __forceinline__ u64 add2_(u64 a, u64 b) {
    u64 d; asm("add.rn.f32x2 %0, %1, %2;" : "=l"(d) : "l"(a), "l"(b)); return d;
}
__device__ __forceinline__ __half2 as_h2(unsigned u) {
    __half2 h; asm("mov.b32 %0, %1;" : "=r"(reinterpret_cast<unsigned&>(h)) : "r"(u)); return h;
}

__global__ __launch_bounds__(NTHR, 1)
void radon_fp_kernel(const float* __restrict__ x, float* __restrict__ out)
{
    extern __shared__ u64 imgs[];
    float2* trig = (float2*)(imgs + SMEM_ELEMS);

    const int tid = threadIdx.x;
    const int bg  = blockIdx.y;          // batch group: batches 4bg .. 4bg+3
    const int sub = tid / 192;           // which of 4 concurrent angles (0..3)
    const int det = tid % 192;

    // Transpose decision: quad's angles span (4q+0.5 .. 4q+3.5)/285 * pi.
    // Transpose when mid-angle is in (pi/4, 3pi/4): (4q+2)/285 in (0.25, 0.75).
    const float am = (4.0f * (float)blockIdx.x + 2.0f) * (1.0f / 285.0f);
    const bool T = (am > 0.25f) & (am < 0.75f);

    const float* gx0 = x + (4 * bg)     * 16384;
    const float* gx1 = x + (4 * bg + 1) * 16384;
    const float* gx2 = x + (4 * bg + 2) * 16384;
    const float* gx3 = x + (4 * bg + 3) * 16384;

    // Fill padded 4-batch fp16 image, optionally transposed.
    // Source coords (sr, sc) = pixel (sr-1, sc-1), border 0; gmem reads stay
    // coalesced either way. Dest: normal sr*131+sc; transposed sc*131+sr
    // (STS lane stride 131 = 3 mod 16 -> conflict-free).
    for (int e = tid; e < 131 * 131; e += NTHR) {
        int sr = e / 131;
        int sc = e - sr * 131;
        int pr = sr - 1, pc = sc - 1;
        bool in = ((unsigned)pr < 128u) & ((unsigned)pc < 128u);
        int gi = pr * 128 + pc;
        float v0 = in ? gx0[gi] : 0.0f;
        float v1 = in ? gx1[gi] : 0.0f;
        float v2 = in ? gx2[gi] : 0.0f;
        float v3 = in ? gx3[gi] : 0.0f;
        __half2 L = __floats2half2_rn(v0, v1);
        __half2 H = __floats2half2_rn(v2, v3);
        unsigned lo = reinterpret_cast<unsigned&>(L);
        unsigned hi = reinterpret_cast<unsigned&>(H);
        int dst = T ? (sc * STRIDE_E + sr) : (sr * STRIDE_E + sc);
        imgs[dst] = ((u64)hi << 32) | (u64)lo;
    }
    // Double-precision trig for this block's 4 angles.
    if (tid < 4) {
        int a = 4 * blockIdx.x + tid;
        if (a < N_ANG) {
            double sd, cd;
            sincospi((a + 0.5) / 285.0, &sd, &cd);
            trig[tid] = make_float2((float)sd, (float)cd);
        }
    }
    __syncthreads();

    // Constants (double-derived)
    const float RHOf = 28.284271247461902f;
    const float KD   = 0.47140452079103173f;        // DT/DX, DX = 0.3125
    const float t0c  = -28.284271247461902f + 0.5f * 0.14731391274719688f;
    const float scale = 0.012276159395599740f;      // DT/12
    const float s = fmaf((float)det + 0.5f, 2.0f * RHOf / 183.0f, -RHOf);

    const u64 BIG2   = pk2( 8388608.f,  8388608.f);
    const u64 nBIG2  = pk2(-8388608.f, -8388608.f);
    const u64 half2c = pk2(0.5f, 0.5f);
    const u64 neg1   = pk2(-1.f, -1.f);
    const u64 one2   = pk2(1.f, 1.f);
    const uint2* img2 = ((const uint2*)imgs) - 132;  // folds +STRIDE+1 base shift

    const int a = 4 * blockIdx.x + sub;
    if (det < N_DET && a < N_ANG) {
        float2 sc = trig[sub];
        float sn = sc.x, cs = sc.y;
        float d0r = KD * cs;
        float d1r = KD * sn;
        // i0 = (-s*sn + t*cs + 20)*3.2 - 0.5, t = t0c + k*DT
        float c0r = fmaf(-s, sn, fmaf(t0c, cs, 20.0f)) * 3.2f - 0.5f;
        float c1r = fmaf( s, cs, fmaf(t0c, sn, 20.0f)) * 3.2f - 0.5f;
        // Axis swap for transposed storage (axis 0 = smem row = 131-stride axis)
        float d0 = T ? d1r : d0r;
        float d1 = T ? d0r : d1r;
        float c0 = T ? c1r : c0r;
        float c1 = T ? c0r : c1r;

        // Valid window (content zero outside i in (-1, 128); safe to 129.49)
        const float LO = -0.999f, HI = 128.01f;
        float ra = (LO - c0) / d0, rb = (HI - c0) / d0;
        float klo = fmaxf(0.0f,  fminf(ra, rb));
        float khi = fminf(383.0f, fmaxf(ra, rb));
        ra = (LO - c1) / d1; rb = (HI - c1) / d1;
        klo = fmaxf(klo, fminf(ra, rb));
        khi = fminf(khi, fmaxf(ra, rb));
        int k0 = (int)ceilf(klo);
        int k1 = (int)floorf(khi);

        u64 d01  = pk2(d0, d1);
        u64 c01m = pk2(c0 + 1.5f, c1 + 1.5f);   // t = i + 1.5
        u64 kf2  = pk2((float)k0, (float)k0);
        u64 accA = 0ull;                        // batches 0,1 (fp32 pair)
        u64 accB = 0ull;                        // batches 2,3

        #pragma unroll 4
        for (int k = k0; k <= k1; ++k) {
            u64 t01  = fma2_(kf2, d01, c01m);        // i+1.5, both axes
            u64 y01  = add2_(t01, BIG2);             // round-to-int in mantissa
            u64 fl01 = add2_(y01, nBIG2);            // round(t) = floor(i)+2
            u64 fr01 = add2_(fma2_(fl01, neg1, t01), half2c); // frac in [0,1]
            kf2 = add2_(kf2, one2);
            int n0 = (int)((unsigned)y01 & 255u);          // floor(i0)+2 in [1,130]
            int n1 = (int)((unsigned)(y01 >> 32) & 255u);  // floor(i1)+2
            int idx = n0 * STRIDE_E + n1;
            uint2 q00 = img2[idx];
            uint2 q01 = img2[idx + 1];
            uint2 q10 = img2[idx + STRIDE_E];
            uint2 q11 = img2[idx + STRIDE_E + 1];
            float f0, f1; upk2(fr01, f0, f1);
            __half2 f0h = __float2half2_rn(f0);
            __half2 f1h = __float2half2_rn(f1);
            // batches 0,1 (low words)
            {
                __half2 a00 = as_h2(q00.x), a01 = as_h2(q01.x);
                __half2 a10 = as_h2(q10.x), a11 = as_h2(q11.x);
                __half2 m0h = __hfma2(f1h, __hsub2(a01, a00), a00);
                __half2 m1h = __hfma2(f1h, __hsub2(a11, a10), a10);
                __half2 r   = __hfma2(f0h, __hsub2(m1h, m0h), m0h);
                accA = add2_(accA, pk2(__low2float(r), __high2float(r)));
            }
            // batches 2,3 (high words)
            {
                __half2 b00 = as_h2(q00.y), b01 = as_h2(q01.y);
                __half2 b10 = as_h2(q10.y), b11 = as_h2(q11.y);
                __half2 m0h = __hfma2(f1h, __hsub2(b01, b00), b00);
                __half2 m1h = __hfma2(f1h, __hsub2(b11, b10), b10);
                __half2 r   = __hfma2(f0h, __hsub2(m1h, m0h), m0h);
                accB = add2_(accB, pk2(__low2float(r), __high2float(r)));
            }
        }

        int ob = ((4 * bg) * N_ANG + a) * N_DET + det;
        float o0, o1, o2, o3;
        upk2(accA, o0, o1);
        upk2(accB, o2, o3);
        out[ob]            = o0 * scale;
        out[ob + SINO]     = o1 * scale;
        out[ob + 2 * SINO] = o2 * scale;
        out[ob + 3 * SINO] = o3 * scale;
    }
}

extern "C" void kernel_launch(void* const* d_in, const int* in_sizes, int n_in,
                              void* d_out, int out_size)
{
    const float* x = (const float*)d_in[0];
    float* out = (float*)d_out;

    static bool attr_set = false;
    if (!attr_set) {
        cudaFuncSetAttribute(radon_fp_kernel,
                             cudaFuncAttributeMaxDynamicSharedMemorySize, SMEM_BYTES);
        attr_set = true;
    }

    dim3 grid(72, 2);    // 72 angle-quads x 2 batch-groups = 144 blocks (1 wave)
    radon_fp_kernel<<<grid, NTHR, SMEM_BYTES>>>(x, out);
}

// round 14
// speedup vs baseline: 1.9567x; 1.0545x over previous
#include <cuda_runtime.h>
#include <cuda_fp16.h>

// Radon forward projection, sm_103a — round 13 (re-bench of R12; R12 bench was
// an infra failure, no signal — same broker error as R4, which re-ran clean).
// Pairwise half2 accumulation: consecutive sample pairs summed via __hadd2,
// one convert + f32x2 accumulate per PAIR -> ~3 fewer slots/iter on the
// binding fma/issue pipes. fp32 accumulators; adaptive transpose kept.

#define STRIDE_E 131
#define SMEM_ELEMS (131 * STRIDE_E)           // 17161 entries (8 B each)
#define SMEM_BYTES (SMEM_ELEMS * 8 + 64)      // + trig table

#define N_ANG 285
#define N_DET 183
#define SINO  (N_ANG * N_DET)                 // 52155
#define NTHR  768

typedef unsigned long long u64;

__device__ __forceinline__ u64 pk2(float x, float y) {
    u64 u; asm("mov.b64 %0, {%1, %2};" : "=l"(u) : "f"(x), "f"(y)); return u;
}
__device__ __forceinline__ void upk2(u64 u, float& x, float& y) {
    asm("mov.b64 {%0, %1}, %2;" : "=f"(x), "=f"(y) : "l"(u));
}
__device__ __forceinline__ u64 fma2_(u64 a, u64 b, u64 c) {
    u64 d; asm("fma.rn.f32x2 %0, %1, %2, %3;" : "=l"(d) : "l"(a), "l"(b), "l"(c)); return d;
}
__device__ __forceinline__ u64 add2_(u64 a, u64 b) {
    u64 d; asm("add.rn.f32x2 %0, %1, %2;" : "=l"(d) : "l"(a), "l"(b)); return d;
}
__device__ __forceinline__ __half2 as_h2(unsigned u) {
    __half2 h; asm("mov.b32 %0, %1;" : "=r"(reinterpret_cast<unsigned&>(h)) : "r"(u)); return h;
}

__global__ __launch_bounds__(NTHR, 1)
void radon_fp_kernel(const float* __restrict__ x, float* __restrict__ out)
{
    extern __shared__ u64 imgs[];
    float2* trig = (float2*)(imgs + SMEM_ELEMS);

    const int tid = threadIdx.x;
    const int bg  = blockIdx.y;          // batch group: batches 4bg .. 4bg+3
    const int sub = tid / 192;           // which of 4 concurrent angles (0..3)
    const int det = tid % 192;

    // Transpose near-vertical quads (mid-angle in (pi/4, 3pi/4)).
    const float am = (4.0f * (float)blockIdx.x + 2.0f) * (1.0f / 285.0f);
    const bool T = (am > 0.25f) & (am < 0.75f);

    const float* gx0 = x + (4 * bg)     * 16384;
    const float* gx1 = x + (4 * bg + 1) * 16384;
    const float* gx2 = x + (4 * bg + 2) * 16384;
    const float* gx3 = x + (4 * bg + 3) * 16384;

    // Fill padded 4-batch fp16 image, optionally transposed.
    for (int e = tid; e < 131 * 131; e += NTHR) {
        int sr = e / 131;
        int sc = e - sr * 131;
        int pr = sr - 1, pc = sc - 1;
        bool in = ((unsigned)pr < 128u) & ((unsigned)pc < 128u);
        int gi = pr * 128 + pc;
        float v0 = in ? gx0[gi] : 0.0f;
        float v1 = in ? gx1[gi] : 0.0f;
        float v2 = in ? gx2[gi] : 0.0f;
        float v3 = in ? gx3[gi] : 0.0f;
        __half2 L = __floats2half2_rn(v0, v1);
        __half2 H = __floats2half2_rn(v2, v3);
        unsigned lo = reinterpret_cast<unsigned&>(L);
        unsigned hi = reinterpret_cast<unsigned&>(H);
        int dst = T ? (sc * STRIDE_E + sr) : (sr * STRIDE_E + sc);
        imgs[dst] = ((u64)hi << 32) | (u64)lo;
    }
    // Double-precision trig for this block's 4 angles.
    if (tid < 4) {
        int a = 4 * blockIdx.x + tid;
        if (a < N_ANG) {
            double sd, cd;
            sincospi((a + 0.5) / 285.0, &sd, &cd);
            trig[tid] = make_float2((float)sd, (float)cd);
        }
    }
    __syncthreads();

    // Constants (double-derived)
    const float RHOf = 28.284271247461902f;
    const float KD   = 0.47140452079103173f;        // DT/DX, DX = 0.3125
    const float t0c  = -28.284271247461902f + 0.5f * 0.14731391274719688f;
    const float scale = 0.012276159395599740f;      // DT/12
    const float s = fmaf((float)det + 0.5f, 2.0f * RHOf / 183.0f, -RHOf);

    const u64 BIG2   = pk2( 8388608.f,  8388608.f);
    const u64 nBIG2  = pk2(-8388608.f, -8388608.f);
    const u64 half2c = pk2(0.5f, 0.5f);
    const u64 neg1   = pk2(-1.f, -1.f);
    const u64 one2   = pk2(1.f, 1.f);
    const uint2* img2 = ((const uint2*)imgs) - 132;  // folds +STRIDE+1 base shift

    const int a = 4 * blockIdx.x + sub;
    if (det < N_DET && a < N_ANG) {
        float2 sc = trig[sub];
        float sn = sc.x, cs = sc.y;
        float d0r = KD * cs;
        float d1r = KD * sn;
        float c0r = fmaf(-s, sn, fmaf(t0c, cs, 20.0f)) * 3.2f - 0.5f;
        float c1r = fmaf( s, cs, fmaf(t0c, sn, 20.0f)) * 3.2f - 0.5f;
        // Axis swap for transposed storage
        float d0 = T ? d1r : d0r;
        float d1 = T ? d0r : d1r;
        float c0 = T ? c1r : c0r;
        float c1 = T ? c0r : c1r;

        // Valid window (content zero outside i in (-1, 128); safe to 129.49)
        const float LO = -0.999f, HI = 128.01f;
        float ra = (LO - c0) / d0, rb = (HI - c0) / d0;
        float klo = fmaxf(0.0f,  fminf(ra, rb));
        float khi = fminf(383.0f, fmaxf(ra, rb));
        ra = (LO - c1) / d1; rb = (HI - c1) / d1;
        klo = fmaxf(klo, fminf(ra, rb));
        khi = fminf(khi, fmaxf(ra, rb));
        int k0 = (int)ceilf(klo);
        int k1 = (int)floorf(khi);

        u64 d01  = pk2(d0, d1);
        u64 c01m = pk2(c0 + 1.5f, c1 + 1.5f);   // t = i + 1.5
        u64 kf2  = pk2((float)k0, (float)k0);
        u64 accA = 0ull;                        // batches 0,1 (fp32 pair)
        u64 accB = 0ull;                        // batches 2,3

        // One bilinear sample at the given kf2 state -> half2 results.
        auto sample = [&](u64 kf2v, __half2& rA, __half2& rB) {
            u64 t01  = fma2_(kf2v, d01, c01m);
            u64 y01  = add2_(t01, BIG2);
            u64 fl01 = add2_(y01, nBIG2);
            u64 fr01 = add2_(fma2_(fl01, neg1, t01), half2c);
            int n0 = (int)((unsigned)y01 & 255u);
            int n1 = (int)((unsigned)(y01 >> 32) & 255u);
            int idx = n0 * STRIDE_E + n1;
            uint2 q00 = img2[idx];
            uint2 q01 = img2[idx + 1];
            uint2 q10 = img2[idx + STRIDE_E];
            uint2 q11 = img2[idx + STRIDE_E + 1];
            float f0, f1; upk2(fr01, f0, f1);
            __half2 f0h = __float2half2_rn(f0);
            __half2 f1h = __float2half2_rn(f1);
            {
                __half2 a00 = as_h2(q00.x), a01 = as_h2(q01.x);
                __half2 a10 = as_h2(q10.x), a11 = as_h2(q11.x);
                __half2 m0h = __hfma2(f1h, __hsub2(a01, a00), a00);
                __half2 m1h = __hfma2(f1h, __hsub2(a11, a10), a10);
                rA = __hfma2(f0h, __hsub2(m1h, m0h), m0h);
            }
            {
                __half2 b00 = as_h2(q00.y), b01 = as_h2(q01.y);
                __half2 b10 = as_h2(q10.y), b11 = as_h2(q11.y);
                __half2 m0h = __hfma2(f1h, __hsub2(b01, b00), b00);
                __half2 m1h = __hfma2(f1h, __hsub2(b11, b10), b10);
                rB = __hfma2(f0h, __hsub2(m1h, m0h), m0h);
            }
        };

        int k = k0;
        #pragma unroll 2
        for (; k + 1 <= k1; k += 2) {
            __half2 rA0, rB0, rA1, rB1;
            sample(kf2, rA0, rB0);
            kf2 = add2_(kf2, one2);
            sample(kf2, rA1, rB1);
            kf2 = add2_(kf2, one2);
            __half2 sA = __hadd2(rA0, rA1);           // pairwise half sum
            __half2 sB = __hadd2(rB0, rB1);
            accA = add2_(accA, pk2(__low2float(sA), __high2float(sA)));
            accB = add2_(accB, pk2(__low2float(sB), __high2float(sB)));
        }
        if (k <= k1) {                                 // odd tail sample
            __half2 rA0, rB0;
            sample(kf2, rA0, rB0);
            accA = add2_(accA, pk2(__low2float(rA0), __high2float(rA0)));
            accB = add2_(accB, pk2(__low2float(rB0), __high2float(rB0)));
        }

        int ob = ((4 * bg) * N_ANG + a) * N_DET + det;
        float o0, o1, o2, o3;
        upk2(accA, o0, o1);
        upk2(accB, o2, o3);
        out[ob]            = o0 * scale;
        out[ob + SINO]     = o1 * scale;
        out[ob + 2 * SINO] = o2 * scale;
        out[ob + 3 * SINO] = o3 * scale;
    }
}

extern "C" void kernel_launch(void* const* d_in, const int* in_sizes, int n_in,
                              void* d_out, int out_size)
{
    const float* x = (const float*)d_in[0];
    float* out = (float*)d_out;

    static bool attr_set = false;
    if (!attr_set) {
        cudaFuncSetAttribute(radon_fp_kernel,
                             cudaFuncAttributeMaxDynamicSharedMemorySize, SMEM_BYTES);
        attr_set = true;
    }

    dim3 grid(72, 2);    // 72 angle-quads x 2 batch-groups = 144 blocks (1 wave)
    radon_fp_kernel<<<grid, NTHR, SMEM_BYTES>>>(x, out);
}